// round 6
// baseline (speedup 1.0000x reference)
#include <cuda_runtime.h>
#include <cstdint>
#include <cstddef>

#define B_ 4
#define L_ 2048
#define D_ 1024
#define H_ 16
#define HD_ 64
#define NX (B_*L_*D_)

// Scratch (allocation-free rule: __device__ globals)
__device__ float g_qh[NX];          // [b,h,l,hd]  (tf32-rounded, pre-scaled 0.125)
__device__ float g_kh[NX];          // tf32-rounded
__device__ float g_vh[NX];          // tf32-rounded
__device__ float g_ao[NX];          // attention out, [b,l,d], tf32-rounded
__device__ float g_xr[3][NX];       // tf32-rounded q, k, v
__device__ float g_wr[4][D_*D_];    // tf32-rounded Wq, Wk, Wv, Wo

// ---------------- helpers ----------------
__device__ __forceinline__ uint32_t s2u(const void* p) {
    uint32_t a;
    asm("{ .reg .u64 t; cvta.to.shared.u64 t, %1; cvt.u32.u64 %0, t; }" : "=r"(a) : "l"(p));
    return a;
}
__device__ __forceinline__ uint32_t f2tf32(float f) {
    uint32_t u;
    asm("cvt.rna.tf32.f32 %0, %1;" : "=r"(u) : "f"(f));
    return u;
}
__device__ __forceinline__ void mma_tf32_16x8x8(float* c, const uint32_t* a, const uint32_t* b) {
    asm volatile(
        "mma.sync.aligned.m16n8k8.row.col.f32.tf32.tf32.f32 "
        "{%0,%1,%2,%3}, {%4,%5,%6,%7}, {%8,%9}, {%0,%1,%2,%3};"
        : "+f"(c[0]), "+f"(c[1]), "+f"(c[2]), "+f"(c[3])
        : "r"(a[0]), "r"(a[1]), "r"(a[2]), "r"(a[3]), "r"(b[0]), "r"(b[1]));
}

// ---------------- tf32 pre-round passes ----------------
__global__ void __launch_bounds__(256) round_x(const float* __restrict__ q,
        const float* __restrict__ k, const float* __restrict__ v)
{
    const int z = blockIdx.y;
    const float* src = (z == 0) ? q : (z == 1) ? k : v;
    float* dst = g_xr[z];
    int i0 = (blockIdx.x * 256 + threadIdx.x) * 4;
    const int stride = gridDim.x * 1024;
    for (int i = i0; i < NX; i += stride) {
        float4 t = *(const float4*)(src + i);
        t.x = __uint_as_float(f2tf32(t.x));
        t.y = __uint_as_float(f2tf32(t.y));
        t.z = __uint_as_float(f2tf32(t.z));
        t.w = __uint_as_float(f2tf32(t.w));
        *(float4*)(dst + i) = t;
    }
}
__global__ void __launch_bounds__(256) round_w(const float* __restrict__ wq,
        const float* __restrict__ wk, const float* __restrict__ wv,
        const float* __restrict__ wo)
{
    const int z = blockIdx.y;
    const float* src = (z == 0) ? wq : (z == 1) ? wk : (z == 2) ? wv : wo;
    float* dst = g_wr[z];
    int i0 = (blockIdx.x * 256 + threadIdx.x) * 4;
    const int stride = gridDim.x * 1024;
    for (int i = i0; i < D_ * D_; i += stride) {
        float4 t = *(const float4*)(src + i);
        t.x = __uint_as_float(f2tf32(t.x));
        t.y = __uint_as_float(f2tf32(t.y));
        t.z = __uint_as_float(f2tf32(t.z));
        t.w = __uint_as_float(f2tf32(t.w));
        *(float4*)(dst + i) = t;
    }
}

#define ASZ  (128 * 36)
#define GEMM_SMEM (4 * ASZ * 4)
#define NIT  (D_ / 32)

// ---------------- shared GEMM core (tf32 mma.sync, 128x128x32, 8 warps) ----------------
// Operands must be PRE-ROUNDED tf32 values: inner loop is cvt-free.
struct GemmAcc { float a[2][8][4]; };

__device__ __forceinline__ void gemm_core(const float* __restrict__ Xa,
                                          const float* __restrict__ Wb,
                                          float* sm, int tid, GemmAcc& acc)
{
    const int wid = tid >> 5, lane = tid & 31;
    const int wm = wid >> 1, wn = wid & 1;
    const int g = lane >> 2, t4 = lane & 3;

    #pragma unroll
    for (int am = 0; am < 2; am++)
        #pragma unroll
        for (int na = 0; na < 8; na++)
            #pragma unroll
            for (int q = 0; q < 4; q++) acc.a[am][na][q] = 0.f;

    auto load_stage = [&](int ck, int s) {
        float* As = sm + s * ASZ;
        float* Bs = sm + 2 * ASZ + s * ASZ;
        #pragma unroll
        for (int i = 0; i < 4; i++) {
            int id = tid + i * 256;
            int r = id >> 3, u = id & 7;
            uint32_t da = s2u(As + r * 36 + u * 4);
            uint32_t db = s2u(Bs + r * 36 + u * 4);
            asm volatile("cp.async.cg.shared.global [%0], [%1], 16;"
                         :: "r"(da), "l"(Xa + (size_t)r * D_ + ck * 32 + u * 4));
            asm volatile("cp.async.cg.shared.global [%0], [%1], 16;"
                         :: "r"(db), "l"(Wb + (size_t)r * D_ + ck * 32 + u * 4));
        }
        asm volatile("cp.async.commit_group;");
    };

    load_stage(0, 0);

    for (int it = 0; it < NIT; it++) {
        if (it + 1 < NIT) {
            load_stage(it + 1, (it + 1) & 1);
            asm volatile("cp.async.wait_group 1;");
        } else {
            asm volatile("cp.async.wait_group 0;");
        }
        __syncthreads();

        const float* As = sm + (it & 1) * ASZ;
        const float* Bs = sm + 2 * ASZ + (it & 1) * ASZ;

        #pragma unroll
        for (int kk = 0; kk < 4; kk++) {
            const int c0 = kk * 8 + t4;
            uint32_t a[2][4];
            #pragma unroll
            for (int am = 0; am < 2; am++) {
                int r = wm * 32 + am * 16 + g;
                a[am][0] = __float_as_uint(As[r * 36 + c0]);
                a[am][1] = __float_as_uint(As[(r + 8) * 36 + c0]);
                a[am][2] = __float_as_uint(As[r * 36 + c0 + 4]);
                a[am][3] = __float_as_uint(As[(r + 8) * 36 + c0 + 4]);
            }
            uint32_t b[8][2];
            #pragma unroll
            for (int na = 0; na < 8; na++) {
                int n = wn * 64 + na * 8 + g;
                b[na][0] = __float_as_uint(Bs[n * 36 + c0]);
                b[na][1] = __float_as_uint(Bs[n * 36 + c0 + 4]);
            }
            #pragma unroll
            for (int am = 0; am < 2; am++)
                #pragma unroll
                for (int na = 0; na < 8; na++)
                    mma_tf32_16x8x8(acc.a[am][na], a[am], b[na]);
        }
        __syncthreads();
    }
}

// Merged Q/K/V projection: grid (8, 64, 3). Reads pre-rounded g_xr/g_wr.
// Writes head layout [b,h,l,hd], tf32-rounded; Q pre-scaled by 0.125 (exact).
__global__ void __launch_bounds__(256, 2)
gemm_proj3(float* __restrict__ qh, float* __restrict__ kh, float* __restrict__ vh)
{
    extern __shared__ float sm[];
    const int tid = threadIdx.x;
    const int z = blockIdx.z;
    const int m0 = blockIdx.y * 128, n0 = blockIdx.x * 128;

    const float* X = g_xr[z];
    const float* W = g_wr[z];
    float* Y = (z == 0) ? qh : (z == 1) ? kh : vh;
    const float scale = (z == 0) ? 0.125f : 1.0f;

    GemmAcc acc;
    gemm_core(X + (size_t)m0 * D_, W + (size_t)n0 * D_, sm, tid, acc);

    const int wid = tid >> 5, lane = tid & 31;
    const int wm = wid >> 1, wn = wid & 1;
    const int g = lane >> 2, t4 = lane & 3;

    #pragma unroll
    for (int am = 0; am < 2; am++) {
        int r = m0 + wm * 32 + am * 16 + g;
        int b = r >> 11, l = r & 2047;
        #pragma unroll
        for (int na = 0; na < 8; na++) {
            int n = n0 + wn * 64 + na * 8 + 2 * t4;
            int h = n >> 6, hd = n & 63;
            float* p0 = Y + (((size_t)b * H_ + h) * L_ + l) * HD_ + hd;
            p0[0] = __uint_as_float(f2tf32(acc.a[am][na][0])) * scale;
            p0[1] = __uint_as_float(f2tf32(acc.a[am][na][1])) * scale;
            float* p1 = Y + (((size_t)b * H_ + h) * L_ + (l + 8)) * HD_ + hd;
            p1[0] = __uint_as_float(f2tf32(acc.a[am][na][2])) * scale;
            p1[1] = __uint_as_float(f2tf32(acc.a[am][na][3])) * scale;
        }
    }
}

// Output projection: reads pre-rounded ao (g_ao) and g_wr[3]; plain [m,n] output.
__global__ void __launch_bounds__(256, 2)
gemm_out(const float* __restrict__ X, float* __restrict__ Y)
{
    extern __shared__ float sm[];
    const int tid = threadIdx.x;
    const int m0 = blockIdx.y * 128, n0 = blockIdx.x * 128;

    GemmAcc acc;
    gemm_core(X + (size_t)m0 * D_, g_wr[3] + (size_t)n0 * D_, sm, tid, acc);

    const int wid = tid >> 5, lane = tid & 31;
    const int wm = wid >> 1, wn = wid & 1;
    const int g = lane >> 2, t4 = lane & 3;

    #pragma unroll
    for (int am = 0; am < 2; am++) {
        int r = m0 + wm * 32 + am * 16 + g;
        #pragma unroll
        for (int na = 0; na < 8; na++) {
            int n = n0 + wn * 64 + na * 8 + 2 * t4;
            float* p0 = Y + (size_t)r * D_ + n;
            p0[0] = acc.a[am][na][0]; p0[1] = acc.a[am][na][1];
            float* p1 = Y + (size_t)(r + 8) * D_ + n;
            p1[0] = acc.a[am][na][2]; p1[1] = acc.a[am][na][3];
        }
    }
}

// ---------------- tf32 mma.sync flash attention (persistent, snake-balanced) ----------------
#define QP 68
#define KVST (64 * QP)
#define ATTN_SMEM ((128 * QP + 4 * KVST) * 4)
#define NBLK 296

__global__ void __launch_bounds__(128, 2) attn_mma(
        const float* __restrict__ qh, const float* __restrict__ kh,
        const float* __restrict__ vh, float* __restrict__ ao)
{
    extern __shared__ float sm[];
    float* Qs = sm;
    float* KV = sm + 128 * QP;

    const int tid = threadIdx.x;
    const int wid = tid >> 5, lane = tid & 31;
    const int g = lane >> 2, t4 = lane & 3;
    const int p = blockIdx.x;

    const int srcA = (lane & ~3) | (t4 >> 1);
    const int srcB = srcA + 2;

    #pragma unroll 1
    for (int round = 0; round < 4; round++) {
        int rank = (round == 0) ? p
                 : (round == 1) ? (591 - p)
                 : (round == 2) ? (592 + p)
                 : (1183 - p);
        if (rank >= 1024) continue;
        const int qt = 15 - (rank >> 6);     // heavy first
        const int bh = rank & 63;
        const int q0 = qt * 128;

        const float* Qb = qh + ((size_t)bh * L_ + q0) * HD_;
        const float* Kb = kh + (size_t)bh * L_ * HD_;
        const float* Vb = vh + (size_t)bh * L_ * HD_;

        __syncthreads();   // smem free from previous tile

        #pragma unroll
        for (int i = 0; i < 16; i++) {
            int e = tid + i * 128;
            int r = e >> 4, c4 = (e & 15) * 4;
            *(float4*)(Qs + r * QP + c4) = *(const float4*)(Qb + (size_t)r * 64 + c4);
        }

        auto ldkv = [&](int kt, int st) {
            float* Ks = KV + st * 2 * KVST;
            float* Vs = Ks + KVST;
            const float* kg = Kb + (size_t)kt * 64 * 64;
            const float* vg = Vb + (size_t)kt * 64 * 64;
            #pragma unroll
            for (int i = 0; i < 8; i++) {
                int e = tid + i * 128;
                int r = e >> 4, c = (e & 15) * 4;
                asm volatile("cp.async.cg.shared.global [%0], [%1], 16;"
                             :: "r"(s2u(Ks + r * QP + c)), "l"(kg + (size_t)r * 64 + c));
                asm volatile("cp.async.cg.shared.global [%0], [%1], 16;"
                             :: "r"(s2u(Vs + r * QP + c)), "l"(vg + (size_t)r * 64 + c));
            }
            asm volatile("cp.async.commit_group;");
        };

        float mrun[4], lrun[4], O[2][8][4];
        #pragma unroll
        for (int i = 0; i < 4; i++) { mrun[i] = -1e30f; lrun[i] = 0.f; }
        #pragma unroll
        for (int mt = 0; mt < 2; mt++)
            #pragma unroll
            for (int nt = 0; nt < 8; nt++)
                #pragma unroll
                for (int e = 0; e < 4; e++) O[mt][nt][e] = 0.f;

        const int ntiles = 2 * qt + 2;
        ldkv(0, 0);

        for (int kt = 0; kt < ntiles; kt++) {
            asm volatile("cp.async.wait_group 0;");
            __syncthreads();
            if (kt + 1 < ntiles) ldkv(kt + 1, (kt + 1) & 1);
            const float* Ks = KV + (kt & 1) * 2 * KVST;
            const float* Vs = Ks + KVST;

            float S[2][8][4];
            #pragma unroll
            for (int mt = 0; mt < 2; mt++)
                #pragma unroll
                for (int nt = 0; nt < 8; nt++)
                    #pragma unroll
                    for (int e = 0; e < 4; e++) S[mt][nt][e] = 0.f;

            #pragma unroll
            for (int kc = 0; kc < 8; kc++) {
                uint32_t af[2][4];
                #pragma unroll
                for (int mt = 0; mt < 2; mt++) {
                    int r = wid * 32 + mt * 16 + g;
                    af[mt][0] = __float_as_uint(Qs[r * QP + kc * 8 + t4]);
                    af[mt][1] = __float_as_uint(Qs[(r + 8) * QP + kc * 8 + t4]);
                    af[mt][2] = __float_as_uint(Qs[r * QP + kc * 8 + t4 + 4]);
                    af[mt][3] = __float_as_uint(Qs[(r + 8) * QP + kc * 8 + t4 + 4]);
                }
                #pragma unroll
                for (int nt = 0; nt < 8; nt++) {
                    uint32_t bf[2];
                    bf[0] = __float_as_uint(Ks[(nt * 8 + g) * QP + kc * 8 + t4]);
                    bf[1] = __float_as_uint(Ks[(nt * 8 + g) * QP + kc * 8 + t4 + 4]);
                    mma_tf32_16x8x8(S[0][nt], af[0], bf);
                    mma_tf32_16x8x8(S[1][nt], af[1], bf);
                }
            }

            const bool maskt = (kt >= ntiles - 2);
            #pragma unroll
            for (int mt = 0; mt < 2; mt++)
                #pragma unroll
                for (int rr = 0; rr < 2; rr++) {
                    const int si = mt * 2 + rr;
                    const int rowg = q0 + wid * 32 + mt * 16 + rr * 8 + g;
                    float mloc = -1e30f;
                    #pragma unroll
                    for (int nt = 0; nt < 8; nt++)
                        #pragma unroll
                        for (int e = 0; e < 2; e++) {
                            float vv = S[mt][nt][rr * 2 + e];
                            if (maskt && (kt * 64 + nt * 8 + 2 * t4 + e) > rowg) vv = -1e30f;
                            S[mt][nt][rr * 2 + e] = vv;
                            mloc = fmaxf(mloc, vv);
                        }
                    mloc = fmaxf(mloc, __shfl_xor_sync(0xffffffffu, mloc, 1));
                    mloc = fmaxf(mloc, __shfl_xor_sync(0xffffffffu, mloc, 2));
                    float mnew = fmaxf(mrun[si], mloc);
                    float corr = __expf(mrun[si] - mnew);
                    float sum = 0.f;
                    #pragma unroll
                    for (int nt = 0; nt < 8; nt++)
                        #pragma unroll
                        for (int e = 0; e < 2; e++) {
                            float pe = __expf(S[mt][nt][rr * 2 + e] - mnew);
                            S[mt][nt][rr * 2 + e] = pe;
                            sum += pe;
                        }
                    sum += __shfl_xor_sync(0xffffffffu, sum, 1);
                    sum += __shfl_xor_sync(0xffffffffu, sum, 2);
                    lrun[si] = lrun[si] * corr + sum;
                    mrun[si] = mnew;
                    #pragma unroll
                    for (int nt = 0; nt < 8; nt++)
                        #pragma unroll
                        for (int e = 0; e < 2; e++)
                            O[mt][nt][rr * 2 + e] *= corr;
                }

            #pragma unroll
            for (int mt = 0; mt < 2; mt++)
                #pragma unroll
                for (int nt = 0; nt < 8; nt++)
                    #pragma unroll
                    for (int e = 0; e < 4; e++)
                        S[mt][nt][e] = __uint_as_float(f2tf32(S[mt][nt][e]));

            #pragma unroll
            for (int kc = 0; kc < 8; kc++) {
                uint32_t a[2][4];
                #pragma unroll
                for (int mt = 0; mt < 2; mt++) {
                    float v0 = __shfl_sync(0xffffffffu, S[mt][kc][0], srcA);
                    float v1 = __shfl_sync(0xffffffffu, S[mt][kc][1], srcA);
                    float v2 = __shfl_sync(0xffffffffu, S[mt][kc][2], srcA);
                    float v3 = __shfl_sync(0xffffffffu, S[mt][kc][3], srcA);
                    float w0 = __shfl_sync(0xffffffffu, S[mt][kc][0], srcB);
                    float w1 = __shfl_sync(0xffffffffu, S[mt][kc][1], srcB);
                    float w2 = __shfl_sync(0xffffffffu, S[mt][kc][2], srcB);
                    float w3 = __shfl_sync(0xffffffffu, S[mt][kc][3], srcB);
                    a[mt][0] = __float_as_uint((t4 & 1) ? v1 : v0);
                    a[mt][1] = __float_as_uint((t4 & 1) ? v3 : v2);
                    a[mt][2] = __float_as_uint((t4 & 1) ? w1 : w0);
                    a[mt][3] = __float_as_uint((t4 & 1) ? w3 : w2);
                }
                #pragma unroll
                for (int nt = 0; nt < 8; nt++) {
                    uint32_t bf[2];
                    bf[0] = __float_as_uint(Vs[(kc * 8 + t4) * QP + nt * 8 + g]);
                    bf[1] = __float_as_uint(Vs[(kc * 8 + t4 + 4) * QP + nt * 8 + g]);
                    mma_tf32_16x8x8(O[0][nt], a[0], bf);
                    mma_tf32_16x8x8(O[1][nt], a[1], bf);
                }
            }
        }

        // ---- epilogue: normalize + tf32-round + write [b, l, d] ----
        const int b = bh >> 4, h = bh & 15;
        #pragma unroll
        for (int mt = 0; mt < 2; mt++)
            #pragma unroll
            for (int rr = 0; rr < 2; rr++) {
                const int si = mt * 2 + rr;
                float inv = 1.f / lrun[si];
                int row = q0 + wid * 32 + mt * 16 + rr * 8 + g;
                float* op = ao + ((size_t)b * L_ + row) * D_ + h * 64 + 2 * t4;
                #pragma unroll
                for (int nt = 0; nt < 8; nt++) {
                    float2 w;
                    w.x = __uint_as_float(f2tf32(O[mt][nt][rr * 2] * inv));
                    w.y = __uint_as_float(f2tf32(O[mt][nt][rr * 2 + 1] * inv));
                    *(float2*)(op + nt * 8) = w;
                }
            }
    }
}

// ---------------- launch ----------------
extern "C" void kernel_launch(void* const* d_in, const int* in_sizes, int n_in,
                              void* d_out, int out_size)
{
    const float* q  = (const float*)d_in[0];
    const float* k  = (const float*)d_in[1];
    const float* v  = (const float*)d_in[2];
    // d_in[3] = mask (causal tril) — applied analytically
    const float* Wq = (const float*)d_in[4];
    const float* Wk = (const float*)d_in[5];
    const float* Wv = (const float*)d_in[6];
    const float* Wo = (const float*)d_in[7];
    float* out = (float*)d_out;

    float *qh, *kh, *vh, *ao;
    cudaGetSymbolAddress((void**)&qh, g_qh);
    cudaGetSymbolAddress((void**)&kh, g_kh);
    cudaGetSymbolAddress((void**)&vh, g_vh);
    cudaGetSymbolAddress((void**)&ao, g_ao);

    cudaFuncSetAttribute(gemm_proj3, cudaFuncAttributeMaxDynamicSharedMemorySize, GEMM_SMEM);
    cudaFuncSetAttribute(gemm_out, cudaFuncAttributeMaxDynamicSharedMemorySize, GEMM_SMEM);
    cudaFuncSetAttribute(attn_mma, cudaFuncAttributeMaxDynamicSharedMemorySize, ATTN_SMEM);

    round_x<<<dim3(1024, 3), 256>>>(q, k, v);
    round_w<<<dim3(128, 4), 256>>>(Wq, Wk, Wv, Wo);
    gemm_proj3<<<dim3(D_ / 128, (B_ * L_) / 128, 3), 256, GEMM_SMEM>>>(qh, kh, vh);
    attn_mma<<<NBLK, 128, ATTN_SMEM>>>(qh, kh, vh, ao);
    gemm_out<<<dim3(D_ / 128, (B_ * L_) / 128), 256, GEMM_SMEM>>>(ao, out);
}